// round 17
// baseline (speedup 1.0000x reference)
#include <cuda_runtime.h>
#include <math.h>

// NeRF-style renderer: B=1, H=W=200, FOCAL=300, NEAR=2, FAR=6, S=128, F=8.
// SEG=8 threads/pixel, 16 strided samples each, exact width-8 shuffle combine.
// Same per-sample pipeline as R16 (best 20.0us kernel-time): ftz ex2, tanh
// half-arg sigmoid, telescoped depth, dn folded into register density weights.
// SEG=8 retested cleanly (R5's SEG=8 regression was confounded by non-ftz asm).
// Output: color_map [200*200*3] then depth_map [200*200] (fp32).

#define H 200
#define W 200
#define NPIX (H * W)
#define S 128
#define F 8
#define SEG 8
#define SPT (S / SEG)          // 16
#define FOCAL 300.0f
#define NEARP 2.0f
#define FARP 6.0f
#define L2E 1.4426950408889634f

__device__ __forceinline__ float ex2f(float x) {
    float r; asm("ex2.approx.ftz.f32 %0, %1;" : "=f"(r) : "f"(x)); return r;
}
__device__ __forceinline__ float tanhf_hw(float x) {
    float r; asm("tanh.approx.f32 %0, %1;" : "=f"(r) : "f"(x)); return r;
}

__global__ __launch_bounds__(128, 12)
void render_kernel(const float* __restrict__ positions,
                   const float* __restrict__ forwards,
                   const float* __restrict__ ups,
                   const float* __restrict__ normal,
                   const float* __restrict__ Wf,
                   const float* __restrict__ bf,
                   const float* __restrict__ Wd,
                   const float* __restrict__ bd,
                   const float* __restrict__ Wc,
                   const float* __restrict__ bc,
                   float* __restrict__ out)
{
    // ---- shared staging ----
    // sample s = q*SPT + i lives at slot i*SEG + q.
    __shared__ float s_t[S];
    __shared__ float s_dl2[S];         // -delta_raw * log2(e)
    __shared__ float s_Wf[3][F];
    __shared__ float s_WdF[F];
    __shared__ float s_WcFh[F][3];     // +0.5 * Wc_feat  (tanh half-arg)
    __shared__ float s_cam[12];        // right(3), up(3), fwd(3), pos(3)
    __shared__ float s_Wd3[3];
    __shared__ float s_Wc3h[3][3];     // +0.5 * Wc_dir
    __shared__ float s_bch[3];         // +0.5 * bc
    __shared__ float s_bf[F];
    __shared__ float s_bd;

    const int tid = threadIdx.x;

    if (tid < S) {
        float n0 = normal[tid];
        int xi = (tid % SPT) * SEG + (tid / SPT);   // transposed slot
        s_t[xi] = NEARP + n0 * (FARP - NEARP);
        float dl = (tid < S - 1) ? (normal[tid + 1] - n0) * (FARP - NEARP)
                                 : 1e10f;
        s_dl2[xi] = -dl * L2E;
    }
    if (tid < 24) s_Wf[tid / F][tid % F] = Wf[tid];
    if (tid >= 32 && tid < 32 + F) {
        int j = tid - 32;
        s_WdF[j] = Wd[3 + j];
        s_bf[j] = bf[j];
    }
    if (tid >= 40 && tid < 40 + 24) {
        int k = tid - 40;
        s_WcFh[k / 3][k % 3] = 0.5f * Wc[(3 + k / 3) * 3 + (k % 3)];
    }
    if (tid == 0) {
        float ux = ups[0], uy = ups[1], uz = ups[2];
        float fx = forwards[0], fy = forwards[1], fz = forwards[2];
        s_cam[0] = uy * fz - uz * fy;
        s_cam[1] = uz * fx - ux * fz;
        s_cam[2] = ux * fy - uy * fx;
        s_cam[3] = ux; s_cam[4] = uy; s_cam[5] = uz;
        s_cam[6] = fx; s_cam[7] = fy; s_cam[8] = fz;
        s_cam[9] = positions[0]; s_cam[10] = positions[1]; s_cam[11] = positions[2];
        s_Wd3[0] = Wd[0]; s_Wd3[1] = Wd[1]; s_Wd3[2] = Wd[2];
        s_bd = bd[0];
        #pragma unroll
        for (int j = 0; j < 3; j++) {
            s_bch[j] = 0.5f * bc[j];
            #pragma unroll
            for (int i = 0; i < 3; i++) s_Wc3h[j][i] = 0.5f * Wc[j * 3 + i];
        }
    }
    __syncthreads();

    const int gtid = blockIdx.x * blockDim.x + tid;   // 320,000 threads
    const int pix = gtid >> 3;
    const int q = gtid & 7;

    const int h = pix / W;
    const int w = pix - h * W;

    const float a = ((float)h - (H * 0.5f - 0.5f)) * (1.0f / FOCAL);
    const float b = -((float)w - (W * 0.5f - 0.5f)) * (1.0f / FOCAL);

    const float dx = a * s_cam[0] + b * s_cam[3] + s_cam[6];
    const float dy = a * s_cam[1] + b * s_cam[4] + s_cam[7];
    const float dz = a * s_cam[2] + b * s_cam[5] + s_cam[8];
    const float dn = sqrtf(dx * dx + dy * dy + dz * dz);

    const float px = s_cam[9], py = s_cam[10], pz = s_cam[11];

    // per-pixel projections + dn-folded density weights (REGISTERS)
    float dirF[F], baseF[F], wdF_r[F];
    #pragma unroll
    for (int j = 0; j < F; j++) {
        dirF[j]  = dx * s_Wf[0][j] + dy * s_Wf[1][j] + dz * s_Wf[2][j];
        baseF[j] = px * s_Wf[0][j] + py * s_Wf[1][j] + pz * s_Wf[2][j] + s_bf[j];
        wdF_r[j] = dn * s_WdF[j];
    }
    const float dird  = dn * (dx * s_Wd3[0] + dy * s_Wd3[1] + dz * s_Wd3[2]);
    const float based = dn * (px * s_Wd3[0] + py * s_Wd3[1] + pz * s_Wd3[2] + s_bd);

    const float hb0 = dx * s_Wc3h[0][0] + dy * s_Wc3h[1][0] + dz * s_Wc3h[2][0] + s_bch[0];
    const float hb1 = dx * s_Wc3h[0][1] + dy * s_Wc3h[1][1] + dz * s_Wc3h[2][1] + s_bch[1];
    const float hb2 = dx * s_Wc3h[0][2] + dy * s_Wc3h[1][2] + dz * s_Wc3h[2][2] + s_bch[2];

    // ---- local segment compositing (half-transmittance telescope) ----
    float Th = 0.5f;
    float c0 = 0.0f, c1 = 0.0f, c2 = 0.0f;

    #pragma unroll 4
    for (int i = 0; i < SPT; i++) {
        const int xi = i * SEG + q;
        const float t = s_t[xi];

        float f[F];
        #pragma unroll
        for (int j = 0; j < F; j++)
            f[j] = fmaxf(fmaf(t, dirF[j], baseF[j]), 0.0f);

        float d = fmaf(t, dird, based);
        #pragma unroll
        for (int j = 0; j < F; j++)
            d = fmaf(f[j], wdF_r[j], d);
        d = fmaxf(d, 0.0f);

        const float e   = ex2f(d * s_dl2[xi]);
        const float Thn = Th * e;
        const float wh  = Th - Thn;       // 0.5 * wgt
        Th = Thn;

        float x0 = hb0, x1 = hb1, x2 = hb2;
        #pragma unroll
        for (int j = 0; j < F; j++) {
            x0 = fmaf(f[j], s_WcFh[j][0], x0);
            x1 = fmaf(f[j], s_WcFh[j][1], x1);
            x2 = fmaf(f[j], s_WcFh[j][2], x2);
        }
        c0 = fmaf(wh, tanhf_hw(x0), c0);
        c1 = fmaf(wh, tanhf_hw(x1), c1);
        c2 = fmaf(wh, tanhf_hw(x2), c2);
    }

    // complete sigmoid's +0.5 term: sum(0.5*wgt) = 0.5 - Th
    const float half_wsum = 0.5f - Th;
    c0 += half_wsum; c1 += half_wsum; c2 += half_wsum;
    const float T = 2.0f * Th;

    // ---- segmented combine across the 8 threads of this pixel ----
    const unsigned mask = 0xFFFFFFFFu;
    // prefix product: p = prod_{r<q} T_r
    float p = 1.0f;
    #pragma unroll
    for (int r = 0; r < SEG - 1; r++) {
        const float Tr = __shfl_sync(mask, T, r, SEG);
        if (q > r) p *= Tr;
    }
    // full product for depth (multiplicative xor-reduce)
    float Tall = T;
    #pragma unroll
    for (int off = 1; off < SEG; off <<= 1)
        Tall *= __shfl_xor_sync(mask, Tall, off, SEG);

    c0 *= p; c1 *= p; c2 *= p;
    #pragma unroll
    for (int off = 1; off < SEG; off <<= 1) {
        c0 += __shfl_xor_sync(mask, c0, off, SEG);
        c1 += __shfl_xor_sync(mask, c1, off, SEG);
        c2 += __shfl_xor_sync(mask, c2, off, SEG);
    }

    if (q == 0) {
        out[pix * 3 + 0] = c0;
        out[pix * 3 + 1] = c1;
        out[pix * 3 + 2] = c2;
        out[NPIX * 3 + pix] = 1.0f - Tall;
    }
}

extern "C" void kernel_launch(void* const* d_in, const int* in_sizes, int n_in,
                              void* d_out, int out_size)
{
    const float* positions = (const float*)d_in[0];
    const float* forwards  = (const float*)d_in[1];
    const float* ups       = (const float*)d_in[2];
    const float* normal    = (const float*)d_in[3];
    const float* Wf        = (const float*)d_in[4];
    const float* bf        = (const float*)d_in[5];
    const float* Wd        = (const float*)d_in[6];
    const float* bd        = (const float*)d_in[7];
    const float* Wc        = (const float*)d_in[8];
    const float* bc        = (const float*)d_in[9];
    float* out = (float*)d_out;

    const int threads = 128;
    const int blocks = (NPIX * SEG) / threads;   // 2500
    render_kernel<<<blocks, threads>>>(positions, forwards, ups, normal,
                                       Wf, bf, Wd, bd, Wc, bc, out);
}